// round 11
// baseline (speedup 1.0000x reference)
#include <cuda_runtime.h>
#include <math.h>

#define SEQ 2048
#define DMODEL 1024
#define QH 16
#define KVH 4
#define DH 64
#define TOPK 64

typedef unsigned long long u64;

// ---------------- scratch (__device__ globals; no allocations) ----------------
__device__ float2 g_Qff[SEQ * QH * DH];            // 16 MB roped q, float-float
__device__ float2 g_Kff[SEQ * KVH * DH];           // 4 MB  roped k, float-float
__device__ float g_V[SEQ * KVH * DH];              // 2 MB
__device__ float g_AO[SEQ * QH * DH];              // 8 MB
__device__ float g_S[QH * (size_t)SEQ * SEQ];      // 256 MB: score slab per head
__device__ float g_cos[SEQ * 32];
__device__ float g_sin[SEQ * 32];

// ---------------- packed f32x2 primitives (sm_103a FFMA2 path) ----------------
__device__ __forceinline__ u64 pk(float x, float y) {
    u64 r; asm("mov.b64 %0, {%1, %2};" : "=l"(r) : "f"(x), "f"(y)); return r;
}
__device__ __forceinline__ u64 pk1(float x) { return pk(x, x); }
__device__ __forceinline__ void upk(u64 v, float& x, float& y) {
    asm("mov.b64 {%0, %1}, %2;" : "=f"(x), "=f"(y) : "l"(v));
}
__device__ __forceinline__ u64 add2(u64 a, u64 b) {
    u64 r; asm("add.rn.f32x2 %0, %1, %2;" : "=l"(r) : "l"(a), "l"(b)); return r;
}
__device__ __forceinline__ u64 mul2(u64 a, u64 b) {
    u64 r; asm("mul.rn.f32x2 %0, %1, %2;" : "=l"(r) : "l"(a), "l"(b)); return r;
}
__device__ __forceinline__ u64 fma2(u64 a, u64 b, u64 c) {
    u64 r; asm("fma.rn.f32x2 %0, %1, %2, %3;" : "=l"(r) : "l"(a), "l"(b), "l"(c)); return r;
}
__device__ __forceinline__ u64 neg2(u64 a) { return a ^ 0x8000000080000000ull; }

// packed TwoProdFMA + TwoSum accumulate: (H,L) += A*B elementwise on both lanes
__device__ __forceinline__ void ff_mac2(u64& H, u64& L, u64 A, u64 B) {
    u64 p = mul2(A, B);
    u64 e = fma2(A, B, neg2(p));
    u64 s = add2(H, p);
    u64 bb = add2(s, neg2(H));
    u64 nbb = neg2(bb);
    u64 t1 = add2(s, nbb);          // s - bb
    u64 t2 = add2(H, neg2(t1));     // h - (s - bb)
    u64 t3 = add2(p, nbb);          // p - bb
    H = s;
    L = add2(L, add2(add2(t2, t3), e));
}

// scalar ff (kept for reference renormalization semantics)
__device__ __forceinline__ void ff_mac(float& h, float& l, float a, float b) {
    float p = a * b;
    float e = fmaf(a, b, -p);
    float s = h + p;
    float bb = s - h;
    float err = (h - (s - bb)) + (p - bb);
    h = s;
    l += err + e;
}

// ---------------- RoPE table: bit-match the reference's f32 op chain ----------------
__global__ void rope_table_kernel() {
    int idx = blockIdx.x * blockDim.x + threadIdx.x;
    if (idx >= SEQ * 32) return;
    int i = idx & 31;
    int pos = idx >> 5;
    float p32 = (float)pow(10000.0, (double)i / 32.0);
    float invf = 1.0f / p32;
    float ang = (float)pos * invf;
    const double TWO_PI = 6.283185307179586476925286766559;
    double dr = (double)ang;
    dr -= TWO_PI * floor(dr / TWO_PI + 0.5);
    g_cos[idx] = (float)cos(dr);
    g_sin[idx] = (float)sin(dr);
}

// ---------------- tiled NT GEMM -> float-float output, f32x2-packed ----------------
__global__ __launch_bounds__(256) void gemm_nt_ff(const float* __restrict__ A,
                                                  const float* __restrict__ B,
                                                  float2* __restrict__ C,
                                                  int M, int N, int K) {
    __shared__ float As[16][68];
    __shared__ float Bs[16][68];
    int bm = blockIdx.y * 64, bn = blockIdx.x * 64;
    int tid = threadIdx.x;
    int tx = tid & 15, ty = tid >> 4;
    u64 AH[4][2] = {}, AL[4][2] = {};
    for (int k0 = 0; k0 < K; k0 += 16) {
#pragma unroll
        for (int t = 0; t < 4; t++) {
            int idx = tid + t * 256;
            int r = idx >> 4, kk = idx & 15;
            As[kk][r] = A[(size_t)(bm + r) * K + k0 + kk];
            Bs[kk][r] = B[(size_t)(bn + r) * K + k0 + kk];
        }
        __syncthreads();
#pragma unroll
        for (int kk = 0; kk < 16; kk++) {
            u64 a2[4], b2[2];
#pragma unroll
            for (int i = 0; i < 4; i++) a2[i] = pk1(As[kk][ty * 4 + i]);
#pragma unroll
            for (int jp = 0; jp < 2; jp++)
                b2[jp] = pk(Bs[kk][tx * 4 + 2 * jp], Bs[kk][tx * 4 + 2 * jp + 1]);
#pragma unroll
            for (int i = 0; i < 4; i++)
#pragma unroll
                for (int jp = 0; jp < 2; jp++) ff_mac2(AH[i][jp], AL[i][jp], a2[i], b2[jp]);
        }
        __syncthreads();
    }
#pragma unroll
    for (int i = 0; i < 4; i++)
#pragma unroll
        for (int jp = 0; jp < 2; jp++) {
            float h0, h1, l0, l1;
            upk(AH[i][jp], h0, h1);
            upk(AL[i][jp], l0, l1);
            float hh0 = h0 + l0, hh1 = h1 + l1;
            float ll0 = l0 - (hh0 - h0), ll1 = l1 - (hh1 - h1);
            size_t base = (size_t)(bm + ty * 4 + i) * N + bn + tx * 4 + 2 * jp;
            C[base] = make_float2(hh0, ll0);
            C[base + 1] = make_float2(hh1, ll1);
        }
}

// ---------------- tiled NT GEMM fp32, f32x2-packed (V proj, out proj) ----------------
__global__ __launch_bounds__(256) void gemm_nt(const float* __restrict__ A,
                                               const float* __restrict__ B,
                                               float* __restrict__ C,
                                               int M, int N, int K) {
    __shared__ float As[16][68];
    __shared__ float Bs[16][68];
    int bm = blockIdx.y * 64, bn = blockIdx.x * 64;
    int tid = threadIdx.x;
    int tx = tid & 15, ty = tid >> 4;
    u64 acc[4][2] = {};
    for (int k0 = 0; k0 < K; k0 += 16) {
#pragma unroll
        for (int t = 0; t < 4; t++) {
            int idx = tid + t * 256;
            int r = idx >> 4, kk = idx & 15;
            As[kk][r] = A[(size_t)(bm + r) * K + k0 + kk];
            Bs[kk][r] = B[(size_t)(bn + r) * K + k0 + kk];
        }
        __syncthreads();
#pragma unroll
        for (int kk = 0; kk < 16; kk++) {
            u64 a2[4], b2[2];
#pragma unroll
            for (int i = 0; i < 4; i++) a2[i] = pk1(As[kk][ty * 4 + i]);
#pragma unroll
            for (int jp = 0; jp < 2; jp++)
                b2[jp] = pk(Bs[kk][tx * 4 + 2 * jp], Bs[kk][tx * 4 + 2 * jp + 1]);
#pragma unroll
            for (int i = 0; i < 4; i++)
#pragma unroll
                for (int jp = 0; jp < 2; jp++) acc[i][jp] = fma2(a2[i], b2[jp], acc[i][jp]);
        }
        __syncthreads();
    }
#pragma unroll
    for (int i = 0; i < 4; i++)
#pragma unroll
        for (int jp = 0; jp < 2; jp++) {
            float c0, c1;
            upk(acc[i][jp], c0, c1);
            size_t base = (size_t)(bm + ty * 4 + i) * N + bn + tx * 4 + 2 * jp;
            C[base] = c0;
            C[base + 1] = c1;
        }
}

// ---------------- RoPE apply on float-float arrays ----------------
__global__ void rope_ff(float2* __restrict__ X, int n_heads) {
    int idx = blockIdx.x * blockDim.x + threadIdx.x;
    int total = SEQ * n_heads * 32;
    if (idx >= total) return;
    int i = idx % 32;
    int h = (idx / 32) % n_heads;
    int pos = idx / (32 * n_heads);
    double c = (double)g_cos[pos * 32 + i];
    double s = (double)g_sin[pos * 32 + i];
    float2* row = X + (size_t)pos * (n_heads * DH) + h * DH;
    double x1 = (double)row[i].x + (double)row[i].y;
    double x2 = (double)row[i + 32].x + (double)row[i + 32].y;
    double r1 = x1 * c - x2 * s;
    double r2 = x2 * c + x1 * s;
    float h1 = (float)r1, h2 = (float)r2;
    row[i]      = make_float2(h1, (float)(r1 - (double)h1));
    row[i + 32] = make_float2(h2, (float)(r2 - (double)h2));
}

// monotone float->uint map (order-preserving)
__device__ __forceinline__ unsigned fmap(float f) {
    unsigned u = __float_as_uint(f);
    return (u & 0x80000000u) ? ~u : (u | 0x80000000u);
}

// ---------------- score GEMM (ff, f32x2-packed): all 16 heads in one launch ----------------
// dynamic smem: Qh/Ql/Kh/Kl each [64][65] floats = 66560 B total
__global__ __launch_bounds__(256) void score_ff16() {
    extern __shared__ float sm[];
    float (*Qh)[65] = (float(*)[65])sm;
    float (*Ql)[65] = (float(*)[65])(sm + 4160);
    float (*Kh)[65] = (float(*)[65])(sm + 8320);
    float (*Kl)[65] = (float(*)[65])(sm + 12480);
    int tid = threadIdx.x;
    int h = blockIdx.y;
    int t = blockIdx.x;
    int bi = (int)((sqrtf(8.0f * (float)t + 1.0f) - 1.0f) * 0.5f);
    while ((bi + 1) * (bi + 2) / 2 <= t) bi++;
    while (bi * (bi + 1) / 2 > t) bi--;
    int bj = t - bi * (bi + 1) / 2;
    int qi0 = bi * 64, j0 = bj * 64;
    int kvh = h >> 2;
    float* Sh = g_S + (size_t)h * SEQ * SEQ;

    // load tiles transposed: [dim][row]
#pragma unroll
    for (int p = 0; p < 16; p++) {
        int idx = tid + p * 256;
        int d = idx & 63, r = idx >> 6;
        float2 v = g_Qff[(size_t)(qi0 + r) * (QH * DH) + h * DH + d];
        Qh[d][r] = v.x; Ql[d][r] = v.y;
        float2 w = g_Kff[(size_t)(j0 + r) * (KVH * DH) + kvh * DH + d];
        Kh[d][r] = w.x; Kl[d][r] = w.y;
    }
    __syncthreads();

    int tx = tid & 15, ty = tid >> 4;   // rows ty+16i, cols tx+16j (j = 2*jp + lane)
    u64 AH[4][2] = {}, AL[4][2] = {};
#pragma unroll 4
    for (int kk = 0; kk < 64; kk++) {
        u64 qh2[4], ql2[4], kh2[2], kl2[2];
#pragma unroll
        for (int i = 0; i < 4; i++) {
            qh2[i] = pk1(Qh[kk][ty + 16 * i]);
            ql2[i] = pk1(Ql[kk][ty + 16 * i]);
        }
#pragma unroll
        for (int jp = 0; jp < 2; jp++) {
            kh2[jp] = pk(Kh[kk][tx + 32 * jp], Kh[kk][tx + 32 * jp + 16]);
            kl2[jp] = pk(Kl[kk][tx + 32 * jp], Kl[kk][tx + 32 * jp + 16]);
        }
#pragma unroll
        for (int i = 0; i < 4; i++)
#pragma unroll
            for (int jp = 0; jp < 2; jp++) {
                ff_mac2(AH[i][jp], AL[i][jp], qh2[i], kh2[jp]);
                AL[i][jp] = fma2(qh2[i], kl2[jp], AL[i][jp]);
                AL[i][jp] = fma2(ql2[i], kh2[jp], AL[i][jp]);
            }
    }
#pragma unroll
    for (int i = 0; i < 4; i++) {
        int qi = qi0 + ty + 16 * i;
#pragma unroll
        for (int jp = 0; jp < 2; jp++) {
            float h0, h1, l0, l1;
            upk(AH[i][jp], h0, h1);
            upk(AL[i][jp], l0, l1);
            int c0 = j0 + tx + 32 * jp, c1 = c0 + 16;
            if (c0 <= qi) Sh[(size_t)qi * SEQ + c0] = (h0 + l0) * 0.125f;
            if (c1 <= qi) Sh[(size_t)qi * SEQ + c1] = (h1 + l1) * 0.125f;
        }
    }
}

// ---------------- attention phase B: block per (query row, head), one launch ----------------
__global__ __launch_bounds__(256) void attn_row16() {
    __shared__ float sc[SEQ];
    __shared__ int hist[2048];
    __shared__ int psum[256];
    __shared__ unsigned long long buf[256];
    __shared__ unsigned bufrm[8];
    __shared__ unsigned long long wred[8];
    __shared__ unsigned long long s_mx;
    __shared__ float fred[8];
    __shared__ float s_smax, s_den;
    __shared__ unsigned s_thr;
    __shared__ int s_b, s_k, s_cnt;
    __shared__ float4 red4[16][16];

    int tid = threadIdx.x, lane = tid & 31, wid = tid >> 5;
    int qi = blockIdx.x;
    int h = blockIdx.y;
    int kvh = h >> 2;
    int len = qi + 1;

    const float* Srow = g_S + (size_t)h * SEQ * SEQ + (size_t)qi * SEQ;
    for (int j = tid; j < len; j += 256) sc[j] = Srow[j];
    __syncthreads();

    // ---- row max ----
    {
        float lm = -INFINITY;
        for (int j = tid; j < len; j += 256) lm = fmaxf(lm, sc[j]);
#pragma unroll
        for (int o = 16; o; o >>= 1) lm = fmaxf(lm, __shfl_xor_sync(0xffffffffu, lm, o));
        if (lane == 0) fred[wid] = lm;
        __syncthreads();
        if (tid == 0) {
            float mm = fred[0];
            for (int w = 1; w < 8; w++) mm = fmaxf(mm, fred[w]);
            s_smax = mm;
        }
        __syncthreads();
    }
    float smax = s_smax;

    // ---- exact 64th-largest threshold ----
    unsigned thr = 0;
    if (len > TOPK) {
        for (int i = tid; i < 2048; i += 256) hist[i] = 0;
        __syncthreads();
        for (int j = tid; j < len; j += 256)
            atomicAdd(&hist[fmap(sc[j]) >> 21], 1);
        __syncthreads();
        {
            int cs = 0;
#pragma unroll
            for (int b = 0; b < 8; b++) cs += hist[tid * 8 + b];
            psum[tid] = cs;
        }
        __syncthreads();
        if (tid == 0) {
            int kneed = TOPK, cum = 0, chunk = 0;
            for (int t = 255; t >= 0; t--) {
                if (cum + psum[t] >= kneed) { chunk = t; break; }
                cum += psum[t];
            }
            int b = chunk * 8;
            for (int bb = chunk * 8 + 7; bb >= chunk * 8; bb--) {
                if (cum + hist[bb] >= kneed) { b = bb; break; }
                cum += hist[bb];
            }
            s_b = b;
            s_k = kneed - cum;
        }
        __syncthreads();
        int b1 = s_b, k1 = s_k;

        for (int i = tid; i < 2048; i += 256) hist[i] = 0;
        __syncthreads();
        for (int j = tid; j < len; j += 256) {
            unsigned u = fmap(sc[j]);
            if ((int)(u >> 21) == b1) atomicAdd(&hist[(u >> 10) & 0x7FF], 1);
        }
        __syncthreads();
        {
            int cs = 0;
#pragma unroll
            for (int b = 0; b < 8; b++) cs += hist[tid * 8 + b];
            psum[tid] = cs;
        }
        __syncthreads();
        if (tid == 0) {
            int kneed = k1, cum = 0, chunk = 0;
            for (int t = 255; t >= 0; t--) {
                if (cum + psum[t] >= kneed) { chunk = t; break; }
                cum += psum[t];
            }
            int b = chunk * 8;
            for (int bb = chunk * 8 + 7; bb >= chunk * 8; bb--) {
                if (cum + hist[bb] >= kneed) { b = bb; break; }
                cum += hist[bb];
            }
            s_b = b;
            s_k = kneed - cum;
            s_cnt = 0;
        }
        __syncthreads();
        int b2 = s_b, k2 = s_k;
        unsigned pref = ((unsigned)b1 << 11) | (unsigned)b2;

        if (tid < 8) bufrm[tid] = 0;
        __syncthreads();
        for (int j = tid; j < len; j += 256) {
            unsigned u = fmap(sc[j]);
            if ((u >> 10) == pref) {
                int p = atomicAdd(&s_cnt, 1);
                if (p < 256) buf[p] = ((unsigned long long)u << 11) | (unsigned)j;
            }
        }
        __syncthreads();
        int cnt = s_cnt;

        if (cnt <= 256) {
            for (int p = 0; p < k2; p++) {
                unsigned long long my = 0ull;
                if (tid < cnt && !((bufrm[tid >> 5] >> (tid & 31)) & 1u)) my = buf[tid];
                unsigned long long v = my;
#pragma unroll
                for (int o = 16; o; o >>= 1) {
                    unsigned long long t = __shfl_xor_sync(0xffffffffu, v, o);
                    if (t > v) v = t;
                }
                if (lane == 0) wred[wid] = v;
                __syncthreads();
                if (tid == 0) {
                    unsigned long long mx = wred[0];
                    for (int w = 1; w < 8; w++)
                        if (wred[w] > mx) mx = wred[w];
                    s_mx = mx;
                    if (p == k2 - 1) s_thr = (unsigned)(mx >> 11);
                }
                __syncthreads();
                if (my == s_mx && my != 0ull) bufrm[tid >> 5] |= 1u << (tid & 31);
                __syncthreads();
            }
        } else {
            for (int i = tid; i < 64; i += 256) hist[i] = 0;
            __syncthreads();
            unsigned* rm = (unsigned*)hist;
            for (int p = 0; p < TOPK; p++) {
                unsigned long long local = 0ull;
                for (int j = tid; j < len; j += 256) {
                    if (!((rm[j >> 5] >> (j & 31)) & 1u)) {
                        unsigned long long key =
                            ((unsigned long long)fmap(sc[j]) << 11) | (unsigned)j;
                        if (key > local) local = key;
                    }
                }
#pragma unroll
                for (int o = 16; o; o >>= 1) {
                    unsigned long long t = __shfl_xor_sync(0xffffffffu, local, o);
                    if (t > local) local = t;
                }
                if (lane == 0) wred[wid] = local;
                __syncthreads();
                if (tid == 0) {
                    unsigned long long mx = wred[0];
                    for (int w = 1; w < 8; w++)
                        if (wred[w] > mx) mx = wred[w];
                    int j = (int)(mx & 0x7FFull);
                    rm[j >> 5] |= 1u << (j & 31);
                    if (p == TOPK - 1) s_thr = (unsigned)(mx >> 11);
                }
                __syncthreads();
            }
        }
        thr = s_thr;
    }

    // ---- weights + denominator (deterministic reduction order) ----
    float part = 0.f;
    __syncthreads();
    for (int j = tid; j < len; j += 256) {
        float v = sc[j];
        float wv = (fmap(v) >= thr) ? expf(v - smax) : 0.f;
        sc[j] = wv;
        part += wv;
    }
#pragma unroll
    for (int o = 16; o; o >>= 1) part += __shfl_xor_sync(0xffffffffu, part, o);
    if (lane == 0) fred[wid] = part;
    __syncthreads();
    if (tid == 0) {
        float d = 0.f;
        for (int w = 0; w < 8; w++) d += fred[w];
        s_den = d;
    }
    __syncthreads();
    float inv = 1.f / s_den;

    // ---- AV: 16 j-groups x 16 float4-dims, deterministic tree ----
    {
        int g = tid >> 4, d4 = tid & 15;
        float4 a = make_float4(0.f, 0.f, 0.f, 0.f);
        for (int j = g; j < len; j += 16) {
            float wv = sc[j];
            if (wv != 0.f) {
                float4 vv = *((const float4*)(g_V + (size_t)j * (KVH * DH) + kvh * DH) + d4);
                a.x += wv * vv.x; a.y += wv * vv.y;
                a.z += wv * vv.z; a.w += wv * vv.w;
            }
        }
        red4[g][d4] = a;
    }
    __syncthreads();
    if (tid < 16) {
        float4 a = make_float4(0.f, 0.f, 0.f, 0.f);
        for (int g = 0; g < 16; g++) {
            float4 v = red4[g][tid];
            a.x += v.x; a.y += v.y; a.z += v.z; a.w += v.w;
        }
        a.x *= inv; a.y *= inv; a.z *= inv; a.w *= inv;
        *((float4*)(g_AO + (size_t)qi * (QH * DH) + h * DH) + tid) = a;
    }
}

// ---------------- launch ----------------
extern "C" void kernel_launch(void* const* d_in, const int* in_sizes, int n_in,
                              void* d_out, int out_size) {
    (void)out_size;
    int ixv = -1, big[2] = {-1, -1}, sml[2] = {-1, -1};
    int nb = 0, ns = 0;
    for (int i = 0; i < n_in; i++) {
        if (in_sizes[i] == SEQ * DMODEL && ixv < 0) ixv = i;
        else if (in_sizes[i] == QH * DH * DMODEL && nb < 2) big[nb++] = i;
        else if (in_sizes[i] == KVH * DH * DMODEL && ns < 2) sml[ns++] = i;
    }
    if (ixv < 0 || nb < 2 || ns < 2) {
        ixv = 0; big[0] = 1; big[1] = 4; sml[0] = 2; sml[1] = 3;
    }
    const float* x  = (const float*)d_in[ixv];
    const float* Wq = (const float*)d_in[big[0]];
    const float* Wo = (const float*)d_in[big[1]];
    const float* Wk = (const float*)d_in[sml[0]];
    const float* Wv = (const float*)d_in[sml[1]];
    float* out = (float*)d_out;

    float2 *Qff, *Kff;
    float *V, *AO;
    cudaGetSymbolAddress((void**)&Qff, g_Qff);
    cudaGetSymbolAddress((void**)&Kff, g_Kff);
    cudaGetSymbolAddress((void**)&V, g_V);
    cudaGetSymbolAddress((void**)&AO, g_AO);

    cudaFuncSetAttribute(score_ff16, cudaFuncAttributeMaxDynamicSharedMemorySize, 66560);

    rope_table_kernel<<<(SEQ * 32 + 255) / 256, 256>>>();

    gemm_nt_ff<<<dim3((QH * DH) / 64, SEQ / 64), 256>>>(x, Wq, Qff, SEQ, QH * DH, DMODEL);
    gemm_nt_ff<<<dim3((KVH * DH) / 64, SEQ / 64), 256>>>(x, Wk, Kff, SEQ, KVH * DH, DMODEL);
    gemm_nt<<<dim3((KVH * DH) / 64, SEQ / 64), 256>>>(x, Wv, V, SEQ, KVH * DH, DMODEL);

    rope_ff<<<(SEQ * QH * 32) / 256, 256>>>(Qff, QH);
    rope_ff<<<(SEQ * KVH * 32) / 256, 256>>>(Kff, KVH);

    const int NT = (SEQ / 64) * (SEQ / 64 + 1) / 2;  // 528 triangular tiles
    score_ff16<<<dim3(NT, QH), 256, 66560>>>();
    attn_row16<<<dim3(SEQ, QH), 256>>>();

    gemm_nt<<<dim3(DMODEL / 64, SEQ / 64), 256>>>(AO, Wo, out, SEQ, DMODEL, QH * DH);
}

// round 12
// speedup vs baseline: 1.4203x; 1.4203x over previous
#include <cuda_runtime.h>
#include <math.h>

#define SEQ 2048
#define DMODEL 1024
#define QH 16
#define KVH 4
#define DH 64
#define TOPK 64
#define CCAP 256

// ---------------- scratch (__device__ globals; no allocations) ----------------
__device__ float2 g_Qff[SEQ * QH * DH];            // 16 MB roped q, float-float
__device__ float2 g_Kff[SEQ * KVH * DH];           // 4 MB  roped k, float-float
__device__ float g_Qh32[SEQ * QH * DH];            // 4 MB  hi copy for plain score GEMM
__device__ float g_Kh32[SEQ * KVH * DH];           // 1 MB
__device__ float g_V[SEQ * KVH * DH];              // 2 MB
__device__ float g_AO[SEQ * QH * DH];              // 8 MB
__device__ float g_S[QH * (size_t)SEQ * SEQ];      // 256 MB approx score slab per head
__device__ float g_cos[SEQ * 32];
__device__ float g_sin[SEQ * 32];

// ---------------- float-float primitives ----------------
__device__ __forceinline__ void ff_mac(float& h, float& l, float a, float b) {
    float p = a * b;
    float e = fmaf(a, b, -p);       // exact product error
    float s = h + p;
    float bb = s - h;
    float err = (h - (s - bb)) + (p - bb);
    h = s;
    l += err + e;
}

// ---------------- RoPE table: bit-match the reference's f32 op chain ----------------
__global__ void rope_table_kernel() {
    int idx = blockIdx.x * blockDim.x + threadIdx.x;
    if (idx >= SEQ * 32) return;
    int i = idx & 31;
    int pos = idx >> 5;
    float p32 = (float)pow(10000.0, (double)i / 32.0);
    float invf = 1.0f / p32;
    float ang = (float)pos * invf;
    const double TWO_PI = 6.283185307179586476925286766559;
    double dr = (double)ang;
    dr -= TWO_PI * floor(dr / TWO_PI + 0.5);
    g_cos[idx] = (float)cos(dr);
    g_sin[idx] = (float)sin(dr);
}

// ---------------- tiled NT GEMM -> float-float output (Q,K projections) ----------------
__global__ __launch_bounds__(256) void gemm_nt_ff(const float* __restrict__ A,
                                                  const float* __restrict__ B,
                                                  float2* __restrict__ C,
                                                  int M, int N, int K) {
    __shared__ float As[16][68];
    __shared__ float Bs[16][68];
    int bm = blockIdx.y * 64, bn = blockIdx.x * 64;
    int tid = threadIdx.x;
    int tx = tid & 15, ty = tid >> 4;
    float ah[4][4] = {}, al[4][4] = {};
    for (int k0 = 0; k0 < K; k0 += 16) {
#pragma unroll
        for (int t = 0; t < 4; t++) {
            int idx = tid + t * 256;
            int r = idx >> 4, kk = idx & 15;
            As[kk][r] = A[(size_t)(bm + r) * K + k0 + kk];
            Bs[kk][r] = B[(size_t)(bn + r) * K + k0 + kk];
        }
        __syncthreads();
#pragma unroll
        for (int kk = 0; kk < 16; kk++) {
            float a[4], b[4];
#pragma unroll
            for (int i = 0; i < 4; i++) a[i] = As[kk][ty * 4 + i];
#pragma unroll
            for (int j = 0; j < 4; j++) b[j] = Bs[kk][tx * 4 + j];
#pragma unroll
            for (int i = 0; i < 4; i++)
#pragma unroll
                for (int j = 0; j < 4; j++) ff_mac(ah[i][j], al[i][j], a[i], b[j]);
        }
        __syncthreads();
    }
#pragma unroll
    for (int i = 0; i < 4; i++)
#pragma unroll
        for (int j = 0; j < 4; j++) {
            float hh = ah[i][j] + al[i][j];               // renormalize
            float ll = al[i][j] - (hh - ah[i][j]);
            C[(size_t)(bm + ty * 4 + i) * N + bn + tx * 4 + j] = make_float2(hh, ll);
        }
}

// ---------------- tiled NT GEMM fp32 (V proj, out proj) ----------------
__global__ __launch_bounds__(256) void gemm_nt(const float* __restrict__ A,
                                               const float* __restrict__ B,
                                               float* __restrict__ C,
                                               int M, int N, int K) {
    __shared__ float As[16][68];
    __shared__ float Bs[16][68];
    int bm = blockIdx.y * 64, bn = blockIdx.x * 64;
    int tid = threadIdx.x;
    int tx = tid & 15, ty = tid >> 4;
    float acc[4][4] = {};
    for (int k0 = 0; k0 < K; k0 += 16) {
#pragma unroll
        for (int t = 0; t < 4; t++) {
            int idx = tid + t * 256;
            int r = idx >> 4, kk = idx & 15;
            As[kk][r] = A[(size_t)(bm + r) * K + k0 + kk];
            Bs[kk][r] = B[(size_t)(bn + r) * K + k0 + kk];
        }
        __syncthreads();
#pragma unroll
        for (int kk = 0; kk < 16; kk++) {
            float a[4], b[4];
#pragma unroll
            for (int i = 0; i < 4; i++) a[i] = As[kk][ty * 4 + i];
#pragma unroll
            for (int j = 0; j < 4; j++) b[j] = Bs[kk][tx * 4 + j];
#pragma unroll
            for (int i = 0; i < 4; i++)
#pragma unroll
                for (int j = 0; j < 4; j++) acc[i][j] += a[i] * b[j];
        }
        __syncthreads();
    }
#pragma unroll
    for (int i = 0; i < 4; i++)
#pragma unroll
        for (int j = 0; j < 4; j++)
            C[(size_t)(bm + ty * 4 + i) * N + bn + tx * 4 + j] = acc[i][j];
}

// ---------------- RoPE apply on float-float arrays; also writes hi copy ----------------
__global__ void rope_ff(float2* __restrict__ X, float* __restrict__ Xh, int n_heads) {
    int idx = blockIdx.x * blockDim.x + threadIdx.x;
    int total = SEQ * n_heads * 32;
    if (idx >= total) return;
    int i = idx % 32;
    int h = (idx / 32) % n_heads;
    int pos = idx / (32 * n_heads);
    double c = (double)g_cos[pos * 32 + i];
    double s = (double)g_sin[pos * 32 + i];
    size_t base = (size_t)pos * (n_heads * DH) + h * DH;
    float2* row = X + base;
    double x1 = (double)row[i].x + (double)row[i].y;
    double x2 = (double)row[i + 32].x + (double)row[i + 32].y;
    double r1 = x1 * c - x2 * s;
    double r2 = x2 * c + x1 * s;
    float h1 = (float)r1, h2 = (float)r2;
    row[i]      = make_float2(h1, (float)(r1 - (double)h1));
    row[i + 32] = make_float2(h2, (float)(r2 - (double)h2));
    Xh[base + i] = h1;
    Xh[base + i + 32] = h2;
}

// monotone float->uint map (order-preserving)
__device__ __forceinline__ unsigned fmap(float f) {
    unsigned u = __float_as_uint(f);
    return (u & 0x80000000u) ? ~u : (u | 0x80000000u);
}
// inverse of fmap
__device__ __forceinline__ float funmap(unsigned u) {
    return __uint_as_float((u & 0x80000000u) ? (u & 0x7FFFFFFFu) : ~u);
}

// ---------------- approx score GEMM (plain fp32 on hi parts), 16 heads ----------------
__global__ __launch_bounds__(256) void score_plain16() {
    __shared__ float Qs[64][65];
    __shared__ float Ks[64][65];
    int tid = threadIdx.x;
    int h = blockIdx.y;
    int t = blockIdx.x;
    int bi = (int)((sqrtf(8.0f * (float)t + 1.0f) - 1.0f) * 0.5f);
    while ((bi + 1) * (bi + 2) / 2 <= t) bi++;
    while (bi * (bi + 1) / 2 > t) bi--;
    int bj = t - bi * (bi + 1) / 2;
    int qi0 = bi * 64, j0 = bj * 64;
    int kvh = h >> 2;
    float* Sh = g_S + (size_t)h * SEQ * SEQ;
    const float* Qp = g_Qh32 + (size_t)qi0 * (QH * DH) + h * DH;
    const float* Kp = g_Kh32 + (size_t)j0 * (KVH * DH) + kvh * DH;

#pragma unroll
    for (int p = 0; p < 16; p++) {
        int idx = tid + p * 256;
        int d = idx & 63, r = idx >> 6;
        Qs[d][r] = Qp[(size_t)r * (QH * DH) + d];
        Ks[d][r] = Kp[(size_t)r * (KVH * DH) + d];
    }
    __syncthreads();

    int tx = tid & 15, ty = tid >> 4;
    float acc[4][4] = {};
#pragma unroll 8
    for (int kk = 0; kk < 64; kk++) {
        float a[4], b[4];
#pragma unroll
        for (int i = 0; i < 4; i++) a[i] = Qs[kk][ty + 16 * i];
#pragma unroll
        for (int j = 0; j < 4; j++) b[j] = Ks[kk][tx + 16 * j];
#pragma unroll
        for (int i = 0; i < 4; i++)
#pragma unroll
            for (int j = 0; j < 4; j++) acc[i][j] += a[i] * b[j];
    }
#pragma unroll
    for (int i = 0; i < 4; i++) {
        int qi = qi0 + ty + 16 * i;
#pragma unroll
        for (int j = 0; j < 4; j++) {
            int jj = j0 + tx + 16 * j;
            if (jj <= qi)
                Sh[(size_t)qi * SEQ + jj] = acc[i][j] * 0.125f;
        }
    }
}

// ---------------- attention: approx-select -> exact recompute of candidates ----------------
__global__ __launch_bounds__(256) void attn16() {
    __shared__ float sc[SEQ];
    __shared__ int hist[2048];
    __shared__ int psum[256];
    __shared__ int cidx[CCAP];
    __shared__ float cval[CCAP];
    __shared__ float cwgt[CCAP];
    __shared__ float2 q2s[DH];
    __shared__ float fred[8];
    __shared__ int s_wc[8], s_woff[8];
    __shared__ float s_smax, s_den;
    __shared__ int s_b, s_k, s_cnt;
    __shared__ float4 red4[16][16];

    int tid = threadIdx.x, lane = tid & 31, wid = tid >> 5;
    int qi = blockIdx.x;
    int h = blockIdx.y;
    int kvh = h >> 2;
    int len = qi + 1;

    if (tid < DH) q2s[tid] = g_Qff[(size_t)qi * (QH * DH) + h * DH + tid];

    const float* Srow = g_S + (size_t)h * SEQ * SEQ + (size_t)qi * SEQ;
    for (int j = tid; j < len; j += 256) sc[j] = Srow[j];
    __syncthreads();

    // ---- radix descent on approx scores -> class floor (superset cutoff) ----
    float vlo = -INFINITY;
    if (len > TOPK) {
        for (int i = tid; i < 2048; i += 256) hist[i] = 0;
        __syncthreads();
        for (int j = tid; j < len; j += 256)
            atomicAdd(&hist[fmap(sc[j]) >> 21], 1);
        __syncthreads();
        {
            int cs = 0;
#pragma unroll
            for (int b = 0; b < 8; b++) cs += hist[tid * 8 + b];
            psum[tid] = cs;
        }
        __syncthreads();
        if (tid == 0) {
            int kneed = TOPK, cum = 0, chunk = 0;
            for (int t = 255; t >= 0; t--) {
                if (cum + psum[t] >= kneed) { chunk = t; break; }
                cum += psum[t];
            }
            int b = chunk * 8;
            for (int bb = chunk * 8 + 7; bb >= chunk * 8; bb--) {
                if (cum + hist[bb] >= kneed) { b = bb; break; }
                cum += hist[bb];
            }
            s_b = b;
            s_k = kneed - cum;
        }
        __syncthreads();
        int b1 = s_b, k1 = s_k;

        for (int i = tid; i < 2048; i += 256) hist[i] = 0;
        __syncthreads();
        for (int j = tid; j < len; j += 256) {
            unsigned u = fmap(sc[j]);
            if ((int)(u >> 21) == b1) atomicAdd(&hist[(u >> 10) & 0x7FF], 1);
        }
        __syncthreads();
        {
            int cs = 0;
#pragma unroll
            for (int b = 0; b < 8; b++) cs += hist[tid * 8 + b];
            psum[tid] = cs;
        }
        __syncthreads();
        if (tid == 0) {
            int kneed = k1, cum = 0, chunk = 0;
            for (int t = 255; t >= 0; t--) {
                if (cum + psum[t] >= kneed) { chunk = t; break; }
                cum += psum[t];
            }
            int b = chunk * 8;
            for (int bb = chunk * 8 + 7; bb >= chunk * 8; bb--) {
                if (cum + hist[bb] >= kneed) { b = bb; break; }
                cum += hist[bb];
            }
            s_b = b;
        }
        __syncthreads();
        unsigned pref = ((unsigned)b1 << 11) | (unsigned)s_b;
        vlo = funmap(pref << 10);
    }

    // ---- ordered ballot compaction of candidates (deterministic) ----
    int cnt = 0;
    for (int attempt = 0; attempt < 2; attempt++) {
        float cutoff = (len > TOPK) ? (attempt == 0 ? vlo - 1e-4f : vlo) : -INFINITY;
        if (tid == 0) s_cnt = 0;
        __syncthreads();
        for (int base = 0; base < len; base += 256) {
            int j = base + tid;
            bool p = (j < len) && (sc[j] >= cutoff);
            unsigned ball = __ballot_sync(0xffffffffu, p);
            if (lane == 0) s_wc[wid] = __popc(ball);
            __syncthreads();
            if (tid == 0) {
                int o = s_cnt;
                for (int w = 0; w < 8; w++) { s_woff[w] = o; o += s_wc[w]; }
                s_cnt = o;
            }
            __syncthreads();
            if (p) {
                int pos = s_woff[wid] + __popc(ball & ((1u << lane) - 1u));
                if (pos < CCAP) cidx[pos] = j;
            }
            __syncthreads();
        }
        cnt = s_cnt < CCAP ? s_cnt : CCAP;
        if (s_cnt <= CCAP || len <= TOPK) break;
    }

    // ---- exact ff recompute for candidates (warp per candidate) ----
    for (int t = wid; t < cnt; t += 8) {
        int j = cidx[t];
        const float2* kr = g_Kff + (size_t)j * (KVH * DH) + kvh * DH;
        float2 k1 = kr[lane], k2 = kr[lane + 32];
        float2 qa = q2s[lane], qb = q2s[lane + 32];
        float sh = 0.f, sl = 0.f;
        ff_mac(sh, sl, qa.x, k1.x);
        sl += qa.x * k1.y + qa.y * k1.x;
        ff_mac(sh, sl, qb.x, k2.x);
        sl += qb.x * k2.y + qb.y * k2.x;
#pragma unroll
        for (int o = 16; o; o >>= 1) {
            float oh = __shfl_xor_sync(0xffffffffu, sh, o);
            float ol = __shfl_xor_sync(0xffffffffu, sl, o);
            float s = sh + oh;
            float bb = s - sh;
            float err = (sh - (s - bb)) + (oh - bb);
            sh = s;
            sl += ol + err;
        }
        if (lane == 0) cval[t] = (sh + sl) * 0.125f;
    }
    __syncthreads();

    // ---- smax over candidate exacts (global max is always a candidate) ----
    {
        float lm = (tid < cnt) ? cval[tid] : -INFINITY;
#pragma unroll
        for (int o = 16; o; o >>= 1) lm = fmaxf(lm, __shfl_xor_sync(0xffffffffu, lm, o));
        if (lane == 0) fred[wid] = lm;
        __syncthreads();
        if (tid == 0) {
            float mm = fred[0];
            for (int w = 1; w < 8; w++) mm = fmaxf(mm, fred[w]);
            s_smax = mm;
        }
        __syncthreads();
    }
    float smax = s_smax;

    // ---- exact 64th-largest among candidates via bit search (deterministic) ----
    unsigned myu = (tid < cnt) ? fmap(cval[tid]) : 0u;
    unsigned thru = 0;
    if (len > TOPK) {
        unsigned prefix = 0;
#pragma unroll
        for (int b = 31; b >= 0; b--) {
            unsigned cand = prefix | (1u << b);
            int c = __syncthreads_count((tid < cnt) && (myu >= cand));
            if (c >= TOPK) prefix = cand;
        }
        thru = prefix;  // exact u of the 64th-largest true score; keep u >= thru (ties kept)
    }

    // ---- weights ----
    {
        float w = 0.f;
        if (tid < cnt && myu >= thru) w = expf(cval[tid] - smax);
        cwgt[tid] = w;
    }
    __syncthreads();

    // ---- denominator (fixed order) ----
    {
        float part = cwgt[tid];
#pragma unroll
        for (int o = 16; o; o >>= 1) part += __shfl_xor_sync(0xffffffffu, part, o);
        if (lane == 0) fred[wid] = part;
        __syncthreads();
        if (tid == 0) {
            float d = 0.f;
            for (int w = 0; w < 8; w++) d += fred[w];
            s_den = d;
        }
        __syncthreads();
    }
    float inv = 1.f / s_den;

    // ---- AV over candidate list: 16 groups x 16 float4-dims ----
    {
        int g = tid >> 4, d4 = tid & 15;
        float4 a = make_float4(0.f, 0.f, 0.f, 0.f);
        for (int t = g; t < cnt; t += 16) {
            float wv = cwgt[t];
            if (wv != 0.f) {
                float4 vv = *((const float4*)(g_V + (size_t)cidx[t] * (KVH * DH) + kvh * DH) + d4);
                a.x += wv * vv.x; a.y += wv * vv.y;
                a.z += wv * vv.z; a.w += wv * vv.w;
            }
        }
        red4[g][d4] = a;
    }
    __syncthreads();
    if (tid < 16) {
        float4 a = make_float4(0.f, 0.f, 0.f, 0.f);
        for (int g = 0; g < 16; g++) {
            float4 v = red4[g][tid];
            a.x += v.x; a.y += v.y; a.z += v.z; a.w += v.w;
        }
        a.x *= inv; a.y *= inv; a.z *= inv; a.w *= inv;
        *((float4*)(g_AO + (size_t)qi * (QH * DH) + h * DH) + tid) = a;
    }
}

// ---------------- launch ----------------
extern "C" void kernel_launch(void* const* d_in, const int* in_sizes, int n_in,
                              void* d_out, int out_size) {
    (void)out_size;
    int ixv = -1, big[2] = {-1, -1}, sml[2] = {-1, -1};
    int nb = 0, ns = 0;
    for (int i = 0; i < n_in; i++) {
        if (in_sizes[i] == SEQ * DMODEL && ixv < 0) ixv = i;
        else if (in_sizes[i] == QH * DH * DMODEL && nb < 2) big[nb++] = i;
        else if (in_sizes[i] == KVH * DH * DMODEL && ns < 2) sml[ns++] = i;
    }
    if (ixv < 0 || nb < 2 || ns < 2) {
        ixv = 0; big[0] = 1; big[1] = 4; sml[0] = 2; sml[1] = 3;
    }
    const float* x  = (const float*)d_in[ixv];
    const float* Wq = (const float*)d_in[big[0]];
    const float* Wo = (const float*)d_in[big[1]];
    const float* Wk = (const float*)d_in[sml[0]];
    const float* Wv = (const float*)d_in[sml[1]];
    float* out = (float*)d_out;

    float2 *Qff, *Kff;
    float *V, *AO, *Qh32, *Kh32;
    cudaGetSymbolAddress((void**)&Qff, g_Qff);
    cudaGetSymbolAddress((void**)&Kff, g_Kff);
    cudaGetSymbolAddress((void**)&V, g_V);
    cudaGetSymbolAddress((void**)&AO, g_AO);
    cudaGetSymbolAddress((void**)&Qh32, g_Qh32);
    cudaGetSymbolAddress((void**)&Kh32, g_Kh32);

    rope_table_kernel<<<(SEQ * 32 + 255) / 256, 256>>>();

    gemm_nt_ff<<<dim3((QH * DH) / 64, SEQ / 64), 256>>>(x, Wq, Qff, SEQ, QH * DH, DMODEL);
    gemm_nt_ff<<<dim3((KVH * DH) / 64, SEQ / 64), 256>>>(x, Wk, Kff, SEQ, KVH * DH, DMODEL);
    gemm_nt<<<dim3((KVH * DH) / 64, SEQ / 64), 256>>>(x, Wv, V, SEQ, KVH * DH, DMODEL);

    rope_ff<<<(SEQ * QH * 32) / 256, 256>>>(Qff, Qh32, QH);
    rope_ff<<<(SEQ * KVH * 32) / 256, 256>>>(Kff, Kh32, KVH);

    const int NT = (SEQ / 64) * (SEQ / 64 + 1) / 2;  // 528 triangular tiles
    score_plain16<<<dim3(NT, QH), 256>>>();
    attn16<<<dim3(SEQ, QH), 256>>>();

    gemm_nt<<<dim3(DMODEL / 64, SEQ / 64), 256>>>(AO, Wo, out, SEQ, DMODEL, QH * DH);
}

// round 13
// speedup vs baseline: 1.5192x; 1.0697x over previous
#include <cuda_runtime.h>
#include <math.h>

#define SEQ 2048
#define DMODEL 1024
#define QH 16
#define KVH 4
#define DH 64
#define TOPK 64
#define CCAP 256

// ---------------- scratch (__device__ globals; no allocations) ----------------
__device__ float2 g_Qff[SEQ * QH * DH];            // 16 MB roped q, float-float
__device__ float2 g_Kff[SEQ * KVH * DH];           // 4 MB  roped k, float-float
__device__ float g_Qh32[SEQ * QH * DH];            // 4 MB  hi copy for plain score GEMM
__device__ float g_Kh32[SEQ * KVH * DH];           // 1 MB
__device__ float g_V[SEQ * KVH * DH];              // 2 MB
__device__ float g_AO[SEQ * QH * DH];              // 8 MB
__device__ float g_S[QH * (size_t)SEQ * SEQ];      // 256 MB approx score slab per head
__device__ float g_cos[SEQ * 32];
__device__ float g_sin[SEQ * 32];

// ---------------- float-float primitives ----------------
__device__ __forceinline__ void ff_mac(float& h, float& l, float a, float b) {
    float p = a * b;
    float e = fmaf(a, b, -p);       // exact product error
    float s = h + p;
    float bb = s - h;
    float err = (h - (s - bb)) + (p - bb);
    h = s;
    l += err + e;
}

// ---------------- RoPE table: bit-match the reference's f32 op chain ----------------
__global__ void rope_table_kernel() {
    int idx = blockIdx.x * blockDim.x + threadIdx.x;
    if (idx >= SEQ * 32) return;
    int i = idx & 31;
    int pos = idx >> 5;
    float p32 = (float)pow(10000.0, (double)i / 32.0);
    float invf = 1.0f / p32;
    float ang = (float)pos * invf;
    const double TWO_PI = 6.283185307179586476925286766559;
    double dr = (double)ang;
    dr -= TWO_PI * floor(dr / TWO_PI + 0.5);
    g_cos[idx] = (float)cos(dr);
    g_sin[idx] = (float)sin(dr);
}

// ---------------- tiled NT GEMM -> float-float output (Q,K projections) ----------------
__global__ __launch_bounds__(256) void gemm_nt_ff(const float* __restrict__ A,
                                                  const float* __restrict__ B,
                                                  float2* __restrict__ C,
                                                  int M, int N, int K) {
    __shared__ float As[16][68];
    __shared__ float Bs[16][68];
    int bm = blockIdx.y * 64, bn = blockIdx.x * 64;
    int tid = threadIdx.x;
    int tx = tid & 15, ty = tid >> 4;
    float ah[4][4] = {}, al[4][4] = {};
    for (int k0 = 0; k0 < K; k0 += 16) {
#pragma unroll
        for (int t = 0; t < 4; t++) {
            int idx = tid + t * 256;
            int r = idx >> 4, kk = idx & 15;
            As[kk][r] = A[(size_t)(bm + r) * K + k0 + kk];
            Bs[kk][r] = B[(size_t)(bn + r) * K + k0 + kk];
        }
        __syncthreads();
#pragma unroll
        for (int kk = 0; kk < 16; kk++) {
            float a[4], b[4];
#pragma unroll
            for (int i = 0; i < 4; i++) a[i] = As[kk][ty * 4 + i];
#pragma unroll
            for (int j = 0; j < 4; j++) b[j] = Bs[kk][tx * 4 + j];
#pragma unroll
            for (int i = 0; i < 4; i++)
#pragma unroll
                for (int j = 0; j < 4; j++) ff_mac(ah[i][j], al[i][j], a[i], b[j]);
        }
        __syncthreads();
    }
#pragma unroll
    for (int i = 0; i < 4; i++)
#pragma unroll
        for (int j = 0; j < 4; j++) {
            float hh = ah[i][j] + al[i][j];               // renormalize
            float ll = al[i][j] - (hh - ah[i][j]);
            C[(size_t)(bm + ty * 4 + i) * N + bn + tx * 4 + j] = make_float2(hh, ll);
        }
}

// ---------------- tiled NT GEMM fp32 (V proj, out proj) ----------------
__global__ __launch_bounds__(256) void gemm_nt(const float* __restrict__ A,
                                               const float* __restrict__ B,
                                               float* __restrict__ C,
                                               int M, int N, int K) {
    __shared__ float As[16][68];
    __shared__ float Bs[16][68];
    int bm = blockIdx.y * 64, bn = blockIdx.x * 64;
    int tid = threadIdx.x;
    int tx = tid & 15, ty = tid >> 4;
    float acc[4][4] = {};
    for (int k0 = 0; k0 < K; k0 += 16) {
#pragma unroll
        for (int t = 0; t < 4; t++) {
            int idx = tid + t * 256;
            int r = idx >> 4, kk = idx & 15;
            As[kk][r] = A[(size_t)(bm + r) * K + k0 + kk];
            Bs[kk][r] = B[(size_t)(bn + r) * K + k0 + kk];
        }
        __syncthreads();
#pragma unroll
        for (int kk = 0; kk < 16; kk++) {
            float a[4], b[4];
#pragma unroll
            for (int i = 0; i < 4; i++) a[i] = As[kk][ty * 4 + i];
#pragma unroll
            for (int j = 0; j < 4; j++) b[j] = Bs[kk][tx * 4 + j];
#pragma unroll
            for (int i = 0; i < 4; i++)
#pragma unroll
                for (int j = 0; j < 4; j++) acc[i][j] += a[i] * b[j];
        }
        __syncthreads();
    }
#pragma unroll
    for (int i = 0; i < 4; i++)
#pragma unroll
        for (int j = 0; j < 4; j++)
            C[(size_t)(bm + ty * 4 + i) * N + bn + tx * 4 + j] = acc[i][j];
}

// ---------------- RoPE apply on float-float arrays; also writes hi copy ----------------
__global__ void rope_ff(float2* __restrict__ X, float* __restrict__ Xh, int n_heads) {
    int idx = blockIdx.x * blockDim.x + threadIdx.x;
    int total = SEQ * n_heads * 32;
    if (idx >= total) return;
    int i = idx % 32;
    int h = (idx / 32) % n_heads;
    int pos = idx / (32 * n_heads);
    double c = (double)g_cos[pos * 32 + i];
    double s = (double)g_sin[pos * 32 + i];
    size_t base = (size_t)pos * (n_heads * DH) + h * DH;
    float2* row = X + base;
    double x1 = (double)row[i].x + (double)row[i].y;
    double x2 = (double)row[i + 32].x + (double)row[i + 32].y;
    double r1 = x1 * c - x2 * s;
    double r2 = x2 * c + x1 * s;
    float h1 = (float)r1, h2 = (float)r2;
    row[i]      = make_float2(h1, (float)(r1 - (double)h1));
    row[i + 32] = make_float2(h2, (float)(r2 - (double)h2));
    Xh[base + i] = h1;
    Xh[base + i + 32] = h2;
}

// monotone float->uint map (order-preserving)
__device__ __forceinline__ unsigned fmap(float f) {
    unsigned u = __float_as_uint(f);
    return (u & 0x80000000u) ? ~u : (u | 0x80000000u);
}
// inverse of fmap
__device__ __forceinline__ float funmap(unsigned u) {
    return __uint_as_float((u & 0x80000000u) ? (u & 0x7FFFFFFFu) : ~u);
}

// ---------------- approx score GEMM (plain fp32 on hi parts), 16 heads ----------------
__global__ __launch_bounds__(256) void score_plain16() {
    __shared__ float Qs[64][65];
    __shared__ float Ks[64][65];
    int tid = threadIdx.x;
    int h = blockIdx.y;
    int t = blockIdx.x;
    int bi = (int)((sqrtf(8.0f * (float)t + 1.0f) - 1.0f) * 0.5f);
    while ((bi + 1) * (bi + 2) / 2 <= t) bi++;
    while (bi * (bi + 1) / 2 > t) bi--;
    int bj = t - bi * (bi + 1) / 2;
    int qi0 = bi * 64, j0 = bj * 64;
    int kvh = h >> 2;
    float* Sh = g_S + (size_t)h * SEQ * SEQ;
    const float* Qp = g_Qh32 + (size_t)qi0 * (QH * DH) + h * DH;
    const float* Kp = g_Kh32 + (size_t)j0 * (KVH * DH) + kvh * DH;

#pragma unroll
    for (int p = 0; p < 16; p++) {
        int idx = tid + p * 256;
        int d = idx & 63, r = idx >> 6;
        Qs[d][r] = Qp[(size_t)r * (QH * DH) + d];
        Ks[d][r] = Kp[(size_t)r * (KVH * DH) + d];
    }
    __syncthreads();

    int tx = tid & 15, ty = tid >> 4;
    float acc[4][4] = {};
#pragma unroll 8
    for (int kk = 0; kk < 64; kk++) {
        float a[4], b[4];
#pragma unroll
        for (int i = 0; i < 4; i++) a[i] = Qs[kk][ty + 16 * i];
#pragma unroll
        for (int j = 0; j < 4; j++) b[j] = Ks[kk][tx + 16 * j];
#pragma unroll
        for (int i = 0; i < 4; i++)
#pragma unroll
            for (int j = 0; j < 4; j++) acc[i][j] += a[i] * b[j];
    }
#pragma unroll
    for (int i = 0; i < 4; i++) {
        int qi = qi0 + ty + 16 * i;
#pragma unroll
        for (int j = 0; j < 4; j++) {
            int jj = j0 + tx + 16 * j;
            if (jj <= qi)
                Sh[(size_t)qi * SEQ + jj] = acc[i][j] * 0.125f;
        }
    }
}

// ---------------- attention: parallel radix cutoff -> exact recompute of candidates ----------------
__global__ __launch_bounds__(256) void attn16() {
    __shared__ float sc[SEQ];
    __shared__ int hist[256];
    __shared__ int cidx[CCAP];
    __shared__ float cval[CCAP];
    __shared__ float cwgt[CCAP];
    __shared__ float2 q2s[DH];
    __shared__ float fred[8];
    __shared__ int s_wc[8];
    __shared__ float s_smax, s_den;
    __shared__ int s_b, s_k, s_cnt;
    __shared__ float4 red4[16][16];

    int tid = threadIdx.x, lane = tid & 31, wid = tid >> 5;
    int qi = blockIdx.x;
    int h = blockIdx.y;
    int kvh = h >> 2;
    int len = qi + 1;

    if (tid < DH) q2s[tid] = g_Qff[(size_t)qi * (QH * DH) + h * DH + tid];
    hist[tid] = 0;
    __syncthreads();

    // ---- fused row load + level-1 histogram (bits [31:24]) ----
    const float* Srow = g_S + (size_t)h * SEQ * SEQ + (size_t)qi * SEQ;
    for (int j = tid; j < len; j += 256) {
        float v = Srow[j];
        sc[j] = v;
        atomicAdd(&hist[fmap(v) >> 24], 1);
    }
    __syncthreads();

    float vlo = -INFINITY;
    if (len > TOPK) {
        // ---- level-1: parallel suffix scan, find cutoff bin ----
        {
            int rs = 255 - tid;
            int v1 = hist[rs];
            int x = v1;
#pragma unroll
            for (int o = 1; o < 32; o <<= 1) {
                int y = __shfl_up_sync(0xffffffffu, x, o);
                if (lane >= o) x += y;
            }
            if (lane == 31) s_wc[wid] = x;
            __syncthreads();
            int wo = 0;
            for (int w = 0; w < wid; w++) wo += s_wc[w];
            int incl = x + wo, excl = incl - v1;
            if (incl >= TOPK && excl < TOPK) { s_b = rs; s_k = TOPK - excl; }
            __syncthreads();
        }
        int b1 = s_b, k1 = s_k;

        // ---- level-2 histogram (bits [23:16]) within bin b1 ----
        hist[tid] = 0;
        __syncthreads();
        for (int j = tid; j < len; j += 256) {
            unsigned u = fmap(sc[j]);
            if ((int)(u >> 24) == b1) atomicAdd(&hist[(u >> 16) & 0xFF], 1);
        }
        __syncthreads();
        {
            int rs = 255 - tid;
            int v1 = hist[rs];
            int x = v1;
#pragma unroll
            for (int o = 1; o < 32; o <<= 1) {
                int y = __shfl_up_sync(0xffffffffu, x, o);
                if (lane >= o) x += y;
            }
            if (lane == 31) s_wc[wid] = x;
            __syncthreads();
            int wo = 0;
            for (int w = 0; w < wid; w++) wo += s_wc[w];
            int incl = x + wo, excl = incl - v1;
            if (incl >= k1 && excl < k1) s_b = rs;
            __syncthreads();
        }
        unsigned floorx = ((unsigned)b1 << 24) | ((unsigned)s_b << 16);
        vlo = funmap(floorx);
    }

    // ---- deterministic compaction: per-thread collect + block exclusive scan ----
    int cnt = 0;
    for (int attempt = 0; attempt < 2; attempt++) {
        float cutoff = (len > TOPK) ? (attempt == 0 ? vlo - 1e-4f : vlo) : -INFINITY;
        int lc = 0;
        int lcs[8];
        for (int c = 0; c * 256 + tid < len; c++) {
            int j = c * 256 + tid;
            if (sc[j] >= cutoff) lcs[lc++] = j;
        }
        int x = lc;
#pragma unroll
        for (int o = 1; o < 32; o <<= 1) {
            int y = __shfl_up_sync(0xffffffffu, x, o);
            if (lane >= o) x += y;
        }
        if (lane == 31) s_wc[wid] = x;
        __syncthreads();
        int wo = 0;
        for (int w = 0; w < wid; w++) wo += s_wc[w];
        int off = wo + x - lc;
        if (tid == 0) {
            int t = 0;
            for (int w = 0; w < 8; w++) t += s_wc[w];
            s_cnt = t;
        }
        for (int i = 0; i < lc; i++) {
            int pos = off + i;
            if (pos < CCAP) cidx[pos] = lcs[i];
        }
        __syncthreads();
        cnt = s_cnt < CCAP ? s_cnt : CCAP;
        if (s_cnt <= CCAP || len <= TOPK) break;
        __syncthreads();
    }

    // ---- exact ff recompute for candidates (warp per candidate) ----
    for (int t = wid; t < cnt; t += 8) {
        int j = cidx[t];
        const float2* kr = g_Kff + (size_t)j * (KVH * DH) + kvh * DH;
        float2 k1v = kr[lane], k2v = kr[lane + 32];
        float2 qa = q2s[lane], qb = q2s[lane + 32];
        float sh = 0.f, sl = 0.f;
        ff_mac(sh, sl, qa.x, k1v.x);
        sl += qa.x * k1v.y + qa.y * k1v.x;
        ff_mac(sh, sl, qb.x, k2v.x);
        sl += qb.x * k2v.y + qb.y * k2v.x;
#pragma unroll
        for (int o = 16; o; o >>= 1) {
            float oh = __shfl_xor_sync(0xffffffffu, sh, o);
            float ol = __shfl_xor_sync(0xffffffffu, sl, o);
            float s = sh + oh;
            float bb = s - sh;
            float err = (sh - (s - bb)) + (oh - bb);
            sh = s;
            sl += ol + err;
        }
        if (lane == 0) cval[t] = (sh + sl) * 0.125f;
    }
    __syncthreads();

    // ---- smax over candidate exacts (global max is always a candidate) ----
    {
        float lm = (tid < cnt) ? cval[tid] : -INFINITY;
#pragma unroll
        for (int o = 16; o; o >>= 1) lm = fmaxf(lm, __shfl_xor_sync(0xffffffffu, lm, o));
        if (lane == 0) fred[wid] = lm;
        __syncthreads();
        if (tid == 0) {
            float mm = fred[0];
            for (int w = 1; w < 8; w++) mm = fmaxf(mm, fred[w]);
            s_smax = mm;
        }
        __syncthreads();
    }
    float smax = s_smax;

    // ---- exact 64th-largest among candidates via bit search (deterministic) ----
    unsigned myu = (tid < cnt) ? fmap(cval[tid]) : 0u;
    unsigned thru = 0;
    if (len > TOPK) {
        unsigned prefix = 0;
#pragma unroll
        for (int b = 31; b >= 0; b--) {
            unsigned cand = prefix | (1u << b);
            int c = __syncthreads_count((tid < cnt) && (myu >= cand));
            if (c >= TOPK) prefix = cand;
        }
        thru = prefix;  // exact u of the 64th-largest true score; keep u >= thru (ties kept)
    }

    // ---- weights ----
    {
        float w = 0.f;
        if (tid < cnt && myu >= thru) w = expf(cval[tid] - smax);
        cwgt[tid] = w;
    }
    __syncthreads();

    // ---- denominator (fixed order) ----
    {
        float part = cwgt[tid];
#pragma unroll
        for (int o = 16; o; o >>= 1) part += __shfl_xor_sync(0xffffffffu, part, o);
        if (lane == 0) fred[wid] = part;
        __syncthreads();
        if (tid == 0) {
            float d = 0.f;
            for (int w = 0; w < 8; w++) d += fred[w];
            s_den = d;
        }
        __syncthreads();
    }
    float inv = 1.f / s_den;

    // ---- AV over candidate list: 16 groups x 16 float4-dims ----
    {
        int g = tid >> 4, d4 = tid & 15;
        float4 a = make_float4(0.f, 0.f, 0.f, 0.f);
        for (int t = g; t < cnt; t += 16) {
            float wv = cwgt[t];
            if (wv != 0.f) {
                float4 vv = *((const float4*)(g_V + (size_t)cidx[t] * (KVH * DH) + kvh * DH) + d4);
                a.x += wv * vv.x; a.y += wv * vv.y;
                a.z += wv * vv.z; a.w += wv * vv.w;
            }
        }
        red4[g][d4] = a;
    }
    __syncthreads();
    if (tid < 16) {
        float4 a = make_float4(0.f, 0.f, 0.f, 0.f);
        for (int g = 0; g < 16; g++) {
            float4 v = red4[g][tid];
            a.x += v.x; a.y += v.y; a.z += v.z; a.w += v.w;
        }
        a.x *= inv; a.y *= inv; a.z *= inv; a.w *= inv;
        *((float4*)(g_AO + (size_t)qi * (QH * DH) + h * DH) + tid) = a;
    }
}

// ---------------- launch ----------------
extern "C" void kernel_launch(void* const* d_in, const int* in_sizes, int n_in,
                              void* d_out, int out_size) {
    (void)out_size;
    int ixv = -1, big[2] = {-1, -1}, sml[2] = {-1, -1};
    int nb = 0, ns = 0;
    for (int i = 0; i < n_in; i++) {
        if (in_sizes[i] == SEQ * DMODEL && ixv < 0) ixv = i;
        else if (in_sizes[i] == QH * DH * DMODEL && nb < 2) big[nb++] = i;
        else if (in_sizes[i] == KVH * DH * DMODEL && ns < 2) sml[ns++] = i;
    }
    if (ixv < 0 || nb < 2 || ns < 2) {
        ixv = 0; big[0] = 1; big[1] = 4; sml[0] = 2; sml[1] = 3;
    }
    const float* x  = (const float*)d_in[ixv];
    const float* Wq = (const float*)d_in[big[0]];
    const float* Wo = (const float*)d_in[big[1]];
    const float* Wk = (const float*)d_in[sml[0]];
    const float* Wv = (const float*)d_in[sml[1]];
    float* out = (float*)d_out;

    float2 *Qff, *Kff;
    float *V, *AO, *Qh32, *Kh32;
    cudaGetSymbolAddress((void**)&Qff, g_Qff);
    cudaGetSymbolAddress((void**)&Kff, g_Kff);
    cudaGetSymbolAddress((void**)&V, g_V);
    cudaGetSymbolAddress((void**)&AO, g_AO);
    cudaGetSymbolAddress((void**)&Qh32, g_Qh32);
    cudaGetSymbolAddress((void**)&Kh32, g_Kh32);

    rope_table_kernel<<<(SEQ * 32 + 255) / 256, 256>>>();

    gemm_nt_ff<<<dim3((QH * DH) / 64, SEQ / 64), 256>>>(x, Wq, Qff, SEQ, QH * DH, DMODEL);
    gemm_nt_ff<<<dim3((KVH * DH) / 64, SEQ / 64), 256>>>(x, Wk, Kff, SEQ, KVH * DH, DMODEL);
    gemm_nt<<<dim3((KVH * DH) / 64, SEQ / 64), 256>>>(x, Wv, V, SEQ, KVH * DH, DMODEL);

    rope_ff<<<(SEQ * QH * 32) / 256, 256>>>(Qff, Qh32, QH);
    rope_ff<<<(SEQ * KVH * 32) / 256, 256>>>(Kff, Kh32, KVH);

    const int NT = (SEQ / 64) * (SEQ / 64 + 1) / 2;  // 528 triangular tiles
    score_plain16<<<dim3(NT, QH), 256>>>();
    attn16<<<dim3(SEQ, QH), 256>>>();

    gemm_nt<<<dim3(DMODEL / 64, SEQ / 64), 256>>>(AO, Wo, out, SEQ, DMODEL, QH * DH);
}